// round 1
// baseline (speedup 1.0000x reference)
#include <cuda_runtime.h>
#include <math.h>

#define BC    2
#define LSEQ  2048
#define HIDD  1024
#define NH    16
#define HD    64
#define PFF   4096
#define MROWS (BC * LSEQ)                       // 4096
#define ATT_ELEMS ((size_t)BC * NH * LSEQ * LSEQ) // 134217728

// ---------------- device scratch (static globals; allocation-free) ----------
__device__ float g_q  [MROWS * HIDD];
__device__ float g_k  [MROWS * HIDD];
__device__ float g_v  [MROWS * HIDD];
__device__ float g_ao [MROWS * HIDD];
__device__ float g_h  [MROWS * HIDD];
__device__ float g_ffn[(size_t)MROWS * PFF];
__device__ float g_sc [ATT_ELEMS];              // self-attn scores (512MB)

// ---------------------------------------------------------------------------
// Generic 128x128x8 fp32 GEMM: C = A[M,K] @ B[K,N] (+ bias) (+epilogue)
// MODE 0: C[m,n] = AB + bias                (row-major out)
// MODE 1: attn layout out: C[((b*NH+h)*LSEQ + l)*HD + d], b=m/LSEQ, l=m%LSEQ,
//         h=n/HD, d=n%HD
// MODE 2: relu(AB + bias)
// MODE 3: AB + bias + R[m,n]
// Requires M%128==0, N%128==0, K%8==0.
// ---------------------------------------------------------------------------
template<int MODE>
__global__ void __launch_bounds__(256)
gemm_k(const float* __restrict__ A, const float* __restrict__ B,
       const float* __restrict__ bias, const float* __restrict__ R,
       float* __restrict__ C, int M, int N, int K)
{
    __shared__ float As[8][128];
    __shared__ float Bs[8][128];
    const int t  = threadIdx.x;
    const int m0 = blockIdx.y * 128;
    const int n0 = blockIdx.x * 128;
    const int tx = t & 15;          // 0..15 -> col fragments
    const int ty = t >> 4;          // 0..15 -> row fragments

    const int am = t >> 1;          // 0..127 row in A tile
    const int ak = (t & 1) * 4;     // 0 or 4
    const int bk = t >> 5;          // 0..7
    const int bn = (t & 31) * 4;    // 0..124

    const float* Ag = A + (size_t)(m0 + am) * K + ak;
    const float* Bg = B + (size_t)bk * N + n0 + bn;

    float acc[8][8];
#pragma unroll
    for (int i = 0; i < 8; i++)
#pragma unroll
        for (int j = 0; j < 8; j++) acc[i][j] = 0.f;

    for (int k0 = 0; k0 < K; k0 += 8) {
        float4 av = *(const float4*)(Ag + k0);
        float4 bv = *(const float4*)(Bg + (size_t)k0 * N);
        As[ak + 0][am] = av.x; As[ak + 1][am] = av.y;
        As[ak + 2][am] = av.z; As[ak + 3][am] = av.w;
        *(float4*)&Bs[bk][bn] = bv;
        __syncthreads();
#pragma unroll
        for (int kk = 0; kk < 8; kk++) {
            float4 a0 = *(const float4*)&As[kk][ty * 4];
            float4 a1 = *(const float4*)&As[kk][64 + ty * 4];
            float4 b0 = *(const float4*)&Bs[kk][tx * 4];
            float4 b1 = *(const float4*)&Bs[kk][64 + tx * 4];
            float ar[8] = {a0.x, a0.y, a0.z, a0.w, a1.x, a1.y, a1.z, a1.w};
            float br[8] = {b0.x, b0.y, b0.z, b0.w, b1.x, b1.y, b1.z, b1.w};
#pragma unroll
            for (int i = 0; i < 8; i++)
#pragma unroll
                for (int j = 0; j < 8; j++)
                    acc[i][j] += ar[i] * br[j];
        }
        __syncthreads();
    }

#pragma unroll
    for (int i = 0; i < 8; i++) {
        int m = m0 + ty * 4 + (i & 3) + (i >> 2) * 64;
#pragma unroll
        for (int j = 0; j < 8; j++) {
            int n = n0 + tx * 4 + (j & 3) + (j >> 2) * 64;
            float vv = acc[i][j] + bias[n];
            if (MODE == 2) vv = fmaxf(vv, 0.f);
            if (MODE == 3) vv += R[(size_t)m * N + n];
            if (MODE == 1) {
                int b = m >> 11, l = m & 2047;
                int h = n >> 6,  d = n & 63;
                C[(((size_t)(b * NH + h)) * LSEQ + l) * HD + d] = vv;
            } else {
                C[(size_t)m * N + n] = vv;
            }
        }
    }
}

// ---------------------------------------------------------------------------
// Scores: S[z, q, k] = (Q[z,q,:] . K[z,k,:]) / 8  (+mask), z = b*NH + h
// Q, K in attn layout [z][LSEQ][HD]. 128x128 tile per block, K-dim = 64.
// ---------------------------------------------------------------------------
__global__ void __launch_bounds__(256)
scores_k(const float* __restrict__ Q, const float* __restrict__ Km,
         const int* __restrict__ mask, float* __restrict__ S)
{
    const int z  = blockIdx.z;
    const int b  = z >> 4;
    const int m0 = blockIdx.y * 128;
    const int n0 = blockIdx.x * 128;
    const float* Qb = Q  + (size_t)z * LSEQ * HD;
    const float* Kb = Km + (size_t)z * LSEQ * HD;

    __shared__ float As[16][128];
    __shared__ float Bs[16][128];
    const int t  = threadIdx.x;
    const int tx = t & 15, ty = t >> 4;
    const int r  = t >> 1;           // 0..127
    const int kb = (t & 1) * 8;      // 0 or 8

    float acc[8][8];
#pragma unroll
    for (int i = 0; i < 8; i++)
#pragma unroll
        for (int j = 0; j < 8; j++) acc[i][j] = 0.f;

    for (int k0 = 0; k0 < HD; k0 += 16) {
        float4 q0 = *(const float4*)(Qb + (size_t)(m0 + r) * HD + k0 + kb);
        float4 q1 = *(const float4*)(Qb + (size_t)(m0 + r) * HD + k0 + kb + 4);
        float4 c0 = *(const float4*)(Kb + (size_t)(n0 + r) * HD + k0 + kb);
        float4 c1 = *(const float4*)(Kb + (size_t)(n0 + r) * HD + k0 + kb + 4);
        As[kb + 0][r] = q0.x; As[kb + 1][r] = q0.y; As[kb + 2][r] = q0.z; As[kb + 3][r] = q0.w;
        As[kb + 4][r] = q1.x; As[kb + 5][r] = q1.y; As[kb + 6][r] = q1.z; As[kb + 7][r] = q1.w;
        Bs[kb + 0][r] = c0.x; Bs[kb + 1][r] = c0.y; Bs[kb + 2][r] = c0.z; Bs[kb + 3][r] = c0.w;
        Bs[kb + 4][r] = c1.x; Bs[kb + 5][r] = c1.y; Bs[kb + 6][r] = c1.z; Bs[kb + 7][r] = c1.w;
        __syncthreads();
#pragma unroll
        for (int kk = 0; kk < 16; kk++) {
            float4 a0 = *(const float4*)&As[kk][ty * 4];
            float4 a1 = *(const float4*)&As[kk][64 + ty * 4];
            float4 b0 = *(const float4*)&Bs[kk][tx * 4];
            float4 b1 = *(const float4*)&Bs[kk][64 + tx * 4];
            float ar[8] = {a0.x, a0.y, a0.z, a0.w, a1.x, a1.y, a1.z, a1.w};
            float br[8] = {b0.x, b0.y, b0.z, b0.w, b1.x, b1.y, b1.z, b1.w};
#pragma unroll
            for (int i = 0; i < 8; i++)
#pragma unroll
                for (int j = 0; j < 8; j++)
                    acc[i][j] += ar[i] * br[j];
        }
        __syncthreads();
    }

    const float scale = 0.125f;  // 1/sqrt(64)
#pragma unroll
    for (int i = 0; i < 8; i++) {
        int m = m0 + ty * 4 + (i & 3) + (i >> 2) * 64;
#pragma unroll
        for (int j = 0; j < 8; j++) {
            int n = n0 + tx * 4 + (j & 3) + (j >> 2) * 64;
            float vv = acc[i][j] * scale;
            if (mask[b * LSEQ + n] == 0) vv = -1e30f;
            S[(size_t)z * LSEQ * LSEQ + (size_t)m * LSEQ + n] = vv;
        }
    }
}

// ---------------------------------------------------------------------------
// Row softmax over last dim (LSEQ = 2048), in place. One block per row.
// ---------------------------------------------------------------------------
__global__ void __launch_bounds__(256) softmax_k(float* __restrict__ S)
{
    float* p = S + (size_t)blockIdx.x * LSEQ;
    const int t = threadIdx.x;
    __shared__ float red[8];

    float v[8];
    float mx = -3.4e38f;
#pragma unroll
    for (int i = 0; i < 8; i++) { v[i] = p[t + 256 * i]; mx = fmaxf(mx, v[i]); }
#pragma unroll
    for (int o = 16; o; o >>= 1) mx = fmaxf(mx, __shfl_xor_sync(0xffffffffu, mx, o));
    if ((t & 31) == 0) red[t >> 5] = mx;
    __syncthreads();
    mx = red[0];
#pragma unroll
    for (int i = 1; i < 8; i++) mx = fmaxf(mx, red[i]);

    float s = 0.f;
#pragma unroll
    for (int i = 0; i < 8; i++) { v[i] = __expf(v[i] - mx); s += v[i]; }
#pragma unroll
    for (int o = 16; o; o >>= 1) s += __shfl_xor_sync(0xffffffffu, s, o);
    __syncthreads();
    if ((t & 31) == 0) red[t >> 5] = s;
    __syncthreads();
    s = 0.f;
#pragma unroll
    for (int i = 0; i < 8; i++) s += red[i];

    float inv = 1.0f / s;
#pragma unroll
    for (int i = 0; i < 8; i++) p[t + 256 * i] = v[i] * inv;
}

// ---------------------------------------------------------------------------
// PV: O[b, q, h*64+d] = sum_k P[z,q,k] * V[z,k,d]  (z = b*NH+h)
// Block computes 128 (q) x 64 (d) tile, BK=16.
// ---------------------------------------------------------------------------
__global__ void __launch_bounds__(256)
pv_k(const float* __restrict__ P, const float* __restrict__ V,
     float* __restrict__ O)
{
    const int z  = blockIdx.y;
    const int b  = z >> 4, h = z & 15;
    const int m0 = blockIdx.x * 128;
    const float* Pb = P + (size_t)z * LSEQ * LSEQ;
    const float* Vb = V + (size_t)z * LSEQ * HD;

    __shared__ float As[16][128];
    __shared__ float Bs[16][64];
    const int t  = threadIdx.x;
    const int tx = t & 15, ty = t >> 4;
    const int ar = t >> 1;           // 0..127
    const int ab = (t & 1) * 8;      // 0 or 8
    const int bk = t >> 4;           // 0..15
    const int bn = (t & 15) * 4;     // 0..60

    float acc[8][4];
#pragma unroll
    for (int i = 0; i < 8; i++)
#pragma unroll
        for (int j = 0; j < 4; j++) acc[i][j] = 0.f;

    for (int k0 = 0; k0 < LSEQ; k0 += 16) {
        float4 p0 = *(const float4*)(Pb + (size_t)(m0 + ar) * LSEQ + k0 + ab);
        float4 p1 = *(const float4*)(Pb + (size_t)(m0 + ar) * LSEQ + k0 + ab + 4);
        float4 vv = *(const float4*)(Vb + (size_t)(k0 + bk) * HD + bn);
        As[ab + 0][ar] = p0.x; As[ab + 1][ar] = p0.y; As[ab + 2][ar] = p0.z; As[ab + 3][ar] = p0.w;
        As[ab + 4][ar] = p1.x; As[ab + 5][ar] = p1.y; As[ab + 6][ar] = p1.z; As[ab + 7][ar] = p1.w;
        *(float4*)&Bs[bk][bn] = vv;
        __syncthreads();
#pragma unroll
        for (int kk = 0; kk < 16; kk++) {
            float4 a0 = *(const float4*)&As[kk][ty * 4];
            float4 a1 = *(const float4*)&As[kk][64 + ty * 4];
            float4 b0 = *(const float4*)&Bs[kk][tx * 4];
            float ar8[8] = {a0.x, a0.y, a0.z, a0.w, a1.x, a1.y, a1.z, a1.w};
            float br4[4] = {b0.x, b0.y, b0.z, b0.w};
#pragma unroll
            for (int i = 0; i < 8; i++)
#pragma unroll
                for (int j = 0; j < 4; j++)
                    acc[i][j] += ar8[i] * br4[j];
        }
        __syncthreads();
    }

#pragma unroll
    for (int i = 0; i < 8; i++) {
        int q = m0 + ty * 4 + (i & 3) + (i >> 2) * 64;
#pragma unroll
        for (int j = 0; j < 4; j++) {
            int d = tx * 4 + j;
            O[((size_t)(b * LSEQ + q)) * HIDD + h * HD + d] = acc[i][j];
        }
    }
}

// ---------------------------------------------------------------------------
// LayerNorm over last dim (HIDD = 1024). One block (256 thr) per row.
// ---------------------------------------------------------------------------
__global__ void __launch_bounds__(256)
ln_k(const float* __restrict__ X, const float* __restrict__ gam,
     const float* __restrict__ bet, float* __restrict__ Y)
{
    const float* x = X + (size_t)blockIdx.x * HIDD;
    float*       y = Y + (size_t)blockIdx.x * HIDD;
    const int t = threadIdx.x;
    __shared__ float red[8];

    float v[4];
    float s = 0.f;
#pragma unroll
    for (int i = 0; i < 4; i++) { v[i] = x[t + 256 * i]; s += v[i]; }
#pragma unroll
    for (int o = 16; o; o >>= 1) s += __shfl_xor_sync(0xffffffffu, s, o);
    if ((t & 31) == 0) red[t >> 5] = s;
    __syncthreads();
    s = 0.f;
#pragma unroll
    for (int i = 0; i < 8; i++) s += red[i];
    const float mean = s * (1.0f / HIDD);

    float vs = 0.f;
#pragma unroll
    for (int i = 0; i < 4; i++) { float d = v[i] - mean; vs += d * d; }
#pragma unroll
    for (int o = 16; o; o >>= 1) vs += __shfl_xor_sync(0xffffffffu, vs, o);
    __syncthreads();
    if ((t & 31) == 0) red[t >> 5] = vs;
    __syncthreads();
    vs = 0.f;
#pragma unroll
    for (int i = 0; i < 8; i++) vs += red[i];
    const float inv = rsqrtf(vs * (1.0f / HIDD) + 1e-5f);

#pragma unroll
    for (int i = 0; i < 4; i++) {
        int c = t + 256 * i;
        y[c] = (v[i] - mean) * inv * gam[c] + bet[c];
    }
}

// ---------------------------------------------------------------------------
extern "C" void kernel_launch(void* const* d_in, const int* in_sizes, int n_in,
                              void* d_out, int out_size)
{
    const float* tgt    = (const float*)d_in[0];
    const float* enc    = (const float*)d_in[1];
    const int*   tmask  = (const int*)  d_in[2];
    const int*   smask  = (const int*)  d_in[3];
    const float* sa_wq  = (const float*)d_in[4],  *sa_bq = (const float*)d_in[5];
    const float* sa_wk  = (const float*)d_in[6],  *sa_bk = (const float*)d_in[7];
    const float* sa_wv  = (const float*)d_in[8],  *sa_bv = (const float*)d_in[9];
    const float* sa_wo  = (const float*)d_in[10], *sa_bo = (const float*)d_in[11];
    const float* ea_wq  = (const float*)d_in[12], *ea_bq = (const float*)d_in[13];
    const float* ea_wk  = (const float*)d_in[14], *ea_bk = (const float*)d_in[15];
    const float* ea_wv  = (const float*)d_in[16], *ea_bv = (const float*)d_in[17];
    const float* ea_wo  = (const float*)d_in[18], *ea_bo = (const float*)d_in[19];
    const float* ffn_w1 = (const float*)d_in[20], *ffn_b1 = (const float*)d_in[21];
    const float* ffn_w2 = (const float*)d_in[22], *ffn_b2 = (const float*)d_in[23];
    const float* ln1_g  = (const float*)d_in[24], *ln1_b = (const float*)d_in[25];
    const float* ln2_g  = (const float*)d_in[26], *ln2_b = (const float*)d_in[27];
    const float* ln3_g  = (const float*)d_in[28], *ln3_b = (const float*)d_in[29];

    float* out     = (float*)d_out;
    float* att_out = out + (size_t)BC * LSEQ * HIDD;   // cross-attn probs region

    float *q, *k, *v, *ao, *h, *ffn, *sc;
    cudaGetSymbolAddress((void**)&q,   g_q);
    cudaGetSymbolAddress((void**)&k,   g_k);
    cudaGetSymbolAddress((void**)&v,   g_v);
    cudaGetSymbolAddress((void**)&ao,  g_ao);
    cudaGetSymbolAddress((void**)&h,   g_h);
    cudaGetSymbolAddress((void**)&ffn, g_ffn);
    cudaGetSymbolAddress((void**)&sc,  g_sc);

    const dim3 blk(256);
    const dim3 gp (HIDD / 128, MROWS / 128);        // (8, 32)  projections
    const dim3 gf1(PFF  / 128, MROWS / 128);        // (32, 32) FFN up
    const dim3 gsc(LSEQ / 128, LSEQ / 128, BC * NH);// (16,16,32)
    const dim3 gpv(LSEQ / 128, BC * NH);            // (16, 32)
    const int  nrows_att = BC * NH * LSEQ;          // 65536 softmax rows
    const int  nrows_ln  = MROWS;                   // 4096

    // ---- self-attention ----
    gemm_k<1><<<gp, blk>>>(tgt, sa_wq, sa_bq, nullptr, q, MROWS, HIDD, HIDD);
    gemm_k<1><<<gp, blk>>>(tgt, sa_wk, sa_bk, nullptr, k, MROWS, HIDD, HIDD);
    gemm_k<1><<<gp, blk>>>(tgt, sa_wv, sa_bv, nullptr, v, MROWS, HIDD, HIDD);
    scores_k<<<gsc, blk>>>(q, k, tmask, sc);
    softmax_k<<<nrows_att, blk>>>(sc);
    pv_k<<<gpv, blk>>>(sc, v, ao);
    gemm_k<3><<<gp, blk>>>(ao, sa_wo, sa_bo, tgt, h, MROWS, HIDD, HIDD);
    ln_k<<<nrows_ln, blk>>>(h, ln1_g, ln1_b, h);

    // ---- cross-attention (probs written straight into d_out region) ----
    gemm_k<1><<<gp, blk>>>(h,   ea_wq, ea_bq, nullptr, q, MROWS, HIDD, HIDD);
    gemm_k<1><<<gp, blk>>>(enc, ea_wk, ea_bk, nullptr, k, MROWS, HIDD, HIDD);
    gemm_k<1><<<gp, blk>>>(enc, ea_wv, ea_bv, nullptr, v, MROWS, HIDD, HIDD);
    scores_k<<<gsc, blk>>>(q, k, smask, att_out);
    softmax_k<<<nrows_att, blk>>>(att_out);
    pv_k<<<gpv, blk>>>(att_out, v, ao);
    gemm_k<3><<<gp, blk>>>(ao, ea_wo, ea_bo, h, h, MROWS, HIDD, HIDD);
    ln_k<<<nrows_ln, blk>>>(h, ln2_g, ln2_b, h);

    // ---- FFN ----
    gemm_k<2><<<gf1, blk>>>(h, ffn_w1, ffn_b1, nullptr, ffn, MROWS, PFF, HIDD);
    gemm_k<3><<<gp,  blk>>>(ffn, ffn_w2, ffn_b2, h, h, MROWS, HIDD, PFF);
    ln_k<<<nrows_ln, blk>>>(h, ln3_g, ln3_b, out);
}

// round 3
// speedup vs baseline: 1.3482x; 1.3482x over previous
#include <cuda_runtime.h>
#include <mma.h>
#include <cstdint>
#include <math.h>

using namespace nvcuda;

#define BC    2
#define LSEQ  2048
#define HIDD  1024
#define NH    16
#define HD    64
#define PFF   4096
#define MROWS (BC * LSEQ)
#define ATT_ELEMS ((size_t)BC * NH * LSEQ * LSEQ)

// ---------------- device scratch ----------------
__device__ float g_q  [MROWS * HIDD];
__device__ float g_k  [MROWS * HIDD];
__device__ float g_vt [MROWS * HIDD];        // V in [z][d][l] transposed layout
__device__ float g_ao [MROWS * HIDD];
__device__ float g_h  [MROWS * HIDD];
__device__ float g_ffn[(size_t)MROWS * PFF];
__device__ float g_sc [ATT_ELEMS];           // self-attn scores/probs
__device__ float g_wt [16 * 1024 * 1024];    // transposed weights [N][K]

// ---------------- helpers ----------------
__device__ __forceinline__ uint32_t smem_u32(const void* p) {
    uint32_t a;
    asm("{ .reg .u64 t; cvta.to.shared.u64 t, %1; cvt.u32.u64 %0, t; }"
        : "=r"(a) : "l"(p));
    return a;
}
__device__ __forceinline__ void cp16(uint32_t dst, const float* src) {
    asm volatile("cp.async.cg.shared.global [%0], [%1], 16;"
        :: "r"(dst), "l"(__cvta_generic_to_global(src)));
}

// ---------------------------------------------------------------------------
// wmma tf32 GEMM: D[128 x NT] = A[128,K] @ Bw[NT,K]^T   (A row-major K-major,
// B stored [N][K] so it is col-major for the MMA). 2-stage cp.async pipeline.
// MODE 1: attn-layout out (Q/K proj) + bias
// MODE 2: relu + bias (FFN up)
// MODE 3: bias + residual R (row-major out)
// MODE 4: V-transposed out [z][d][l] + bias
// MODE 5: scores: *0.125, mask, batched
// MODE 6: PV out -> O[b*LSEQ+q][h*64+d], batched
// ---------------------------------------------------------------------------
template<int MODE, int NT>
__global__ void __launch_bounds__(256)
tc_gemm(const float* __restrict__ A, const float* __restrict__ Bw,
        const float* __restrict__ bias, const float* __restrict__ Rres,
        const int* __restrict__ mask, float* __restrict__ C,
        int K, int lda, int ldb, int ncols,
        long long aBatch, long long bBatch)
{
    constexpr int WY  = (NT == 128) ? 2 : 4;
    constexpr int WX  = 8 / WY;
    constexpr int WTM = 128 / WY;       // warp tile M
    constexpr int WTN = NT / WX;        // warp tile N
    constexpr int FM  = WTM / 16;
    constexpr int FN  = WTN / 16;
    constexpr int LDS_ = 36;            // BK=32 + pad
    constexpr int ASZ = 128 * LDS_;
    constexpr int BSZ = NT * LDS_;
    constexpr int STG = NT + 4;

    extern __shared__ float sm[];
    const uint32_t sb = smem_u32(sm);
    const int t = threadIdx.x, w = t >> 5;
    const int wy = w % WY, wx = w / WY;
    const int m0 = blockIdx.y * 128, n0 = blockIdx.x * NT;
    const int z  = blockIdx.z;

    const float* Ab = A  + (size_t)z * aBatch;
    const float* Bb = Bw + (size_t)z * bBatch;

    wmma::fragment<wmma::accumulator, 16, 16, 8, float> cf[FM][FN];
#pragma unroll
    for (int i = 0; i < FM; i++)
#pragma unroll
        for (int j = 0; j < FN; j++) wmma::fill_fragment(cf[i][j], 0.0f);

    auto load_chunk = [&](int ci, int s) {
        const int k0 = ci * 32;
        const uint32_t abase = sb + (uint32_t)(s * (ASZ + BSZ)) * 4u;
#pragma unroll
        for (int j = 0; j < 4; j++) {
            int id = j * 256 + t, row = id >> 3, cc = id & 7;
            cp16(abase + (uint32_t)(row * LDS_ + cc * 4) * 4u,
                 Ab + (size_t)(m0 + row) * lda + k0 + cc * 4);
        }
        const uint32_t bbase = abase + (uint32_t)ASZ * 4u;
#pragma unroll
        for (int j = 0; j < NT / 32; j++) {
            int id = j * 256 + t, row = id >> 3, cc = id & 7;
            cp16(bbase + (uint32_t)(row * LDS_ + cc * 4) * 4u,
                 Bb + (size_t)(n0 + row) * ldb + k0 + cc * 4);
        }
        asm volatile("cp.async.commit_group;");
    };

    const int nch = K / 32;
    load_chunk(0, 0);

    for (int i = 0; i < nch; i++) {
        if (i + 1 < nch) {
            load_chunk(i + 1, (i + 1) & 1);
            asm volatile("cp.async.wait_group 1;");
        } else {
            asm volatile("cp.async.wait_group 0;");
        }
        __syncthreads();
        const float* Ast = sm + (i & 1) * (ASZ + BSZ);
        const float* Bst = Ast + ASZ;
#pragma unroll
        for (int ks = 0; ks < 4; ks++) {
            wmma::fragment<wmma::matrix_a, 16, 16, 8, wmma::precision::tf32, wmma::row_major> af[FM];
            wmma::fragment<wmma::matrix_b, 16, 16, 8, wmma::precision::tf32, wmma::col_major> bf[FN];
#pragma unroll
            for (int fm = 0; fm < FM; fm++) {
                wmma::load_matrix_sync(af[fm], Ast + (wy * WTM + fm * 16) * LDS_ + ks * 8, LDS_);
#pragma unroll
                for (int e = 0; e < af[fm].num_elements; e++)
                    af[fm].x[e] = wmma::__float_to_tf32(af[fm].x[e]);
            }
#pragma unroll
            for (int fn = 0; fn < FN; fn++) {
                wmma::load_matrix_sync(bf[fn], Bst + (wx * WTN + fn * 16) * LDS_ + ks * 8, LDS_);
#pragma unroll
                for (int e = 0; e < bf[fn].num_elements; e++)
                    bf[fn].x[e] = wmma::__float_to_tf32(bf[fn].x[e]);
            }
#pragma unroll
            for (int fm = 0; fm < FM; fm++)
#pragma unroll
                for (int fn = 0; fn < FN; fn++)
                    wmma::mma_sync(cf[fm][fn], af[fm], bf[fn], cf[fm][fn]);
        }
        __syncthreads();
    }

    // ---- epilogue: frags -> smem staging -> coalesced global stores ----
    float* stg = sm;
#pragma unroll
    for (int fm = 0; fm < FM; fm++)
#pragma unroll
        for (int fn = 0; fn < FN; fn++)
            wmma::store_matrix_sync(stg + (wy * WTM + fm * 16) * STG + wx * WTN + fn * 16,
                                    cf[fm][fn], STG, wmma::mem_row_major);
    __syncthreads();

    if (MODE == 4) {
        const int b = m0 >> 11, lbase = m0 & 2047;
#pragma unroll
        for (int p = 0; p < NT / 8; p++) {
            int idx = p * 256 + t;
            int dcol = idx >> 5, lq = idx & 31, l4 = lq * 4;
            int n = n0 + dcol, h = n >> 6, dd = n & 63;
            float bv = __ldg(&bias[n]);
            float4 o;
            o.x = stg[(l4 + 0) * STG + dcol] + bv;
            o.y = stg[(l4 + 1) * STG + dcol] + bv;
            o.z = stg[(l4 + 2) * STG + dcol] + bv;
            o.w = stg[(l4 + 3) * STG + dcol] + bv;
            *(float4*)&C[(((size_t)(b * NH + h)) * HD + dd) * LSEQ + lbase + l4] = o;
        }
    } else {
        constexpr int QPR = NT / 4;     // float4 per row
#pragma unroll
        for (int p = 0; p < (128 * QPR) / 256; p++) {
            int idx = p * 256 + t;
            int rr = idx / QPR;
            int cq = (idx % QPR) * 4;
            float vv[4];
#pragma unroll
            for (int c2 = 0; c2 < 4; c2++) {
                float v = stg[rr * STG + cq + c2];
                int n = n0 + cq + c2;
                if (MODE == 1 || MODE == 2 || MODE == 3) v += __ldg(&bias[n]);
                if (MODE == 2) v = fmaxf(v, 0.f);
                if (MODE == 5) {
                    v *= 0.125f;
                    if (__ldg(&mask[(z >> 4) * LSEQ + n]) == 0) v = -1e30f;
                }
                vv[c2] = v;
            }
            float4 o = {vv[0], vv[1], vv[2], vv[3]};
            int n = n0 + cq;
            if (MODE == 3) {
                const float4 rv = *(const float4*)&Rres[(size_t)(m0 + rr) * ncols + n];
                o.x += rv.x; o.y += rv.y; o.z += rv.z; o.w += rv.w;
                *(float4*)&C[(size_t)(m0 + rr) * ncols + n] = o;
            } else if (MODE == 1) {
                int m = m0 + rr, b = m >> 11, l = m & 2047;
                int h = n >> 6, d = n & 63;
                *(float4*)&C[(((size_t)(b * NH + h)) * LSEQ + l) * HD + d] = o;
            } else if (MODE == 5) {
                *(float4*)&C[(size_t)z * LSEQ * LSEQ + (size_t)(m0 + rr) * LSEQ + n] = o;
            } else if (MODE == 6) {
                int b = z >> 4, h = z & 15;
                *(float4*)&C[((size_t)(b * LSEQ + m0 + rr)) * HIDD + h * HD + n] = o;
            } else {
                *(float4*)&C[(size_t)(m0 + rr) * ncols + n] = o;
            }
        }
    }
}

// ---------------------------------------------------------------------------
// Weight transpose: Wt[n][k] = W[k][n],  W is [Rk x Cn]
// ---------------------------------------------------------------------------
__global__ void transpose_k(const float* __restrict__ W, float* __restrict__ Wt,
                            int Rk, int Cn)
{
    __shared__ float tile[32][33];
    const int c0 = blockIdx.x * 32, r0 = blockIdx.y * 32;
    const int x = threadIdx.x, y = threadIdx.y;
#pragma unroll
    for (int j = 0; j < 32; j += 8)
        tile[y + j][x] = W[(size_t)(r0 + y + j) * Cn + c0 + x];
    __syncthreads();
#pragma unroll
    for (int j = 0; j < 32; j += 8)
        Wt[(size_t)(c0 + y + j) * Rk + r0 + x] = tile[x][y + j];
}

// ---------------------------------------------------------------------------
// Row softmax over LSEQ=2048, in place.
// ---------------------------------------------------------------------------
__global__ void __launch_bounds__(256) softmax_k(float* __restrict__ S)
{
    float* p = S + (size_t)blockIdx.x * LSEQ;
    const int t = threadIdx.x;
    __shared__ float red[8];

    float v[8];
    float mx = -3.4e38f;
#pragma unroll
    for (int i = 0; i < 8; i++) { v[i] = p[t + 256 * i]; mx = fmaxf(mx, v[i]); }
#pragma unroll
    for (int o = 16; o; o >>= 1) mx = fmaxf(mx, __shfl_xor_sync(0xffffffffu, mx, o));
    if ((t & 31) == 0) red[t >> 5] = mx;
    __syncthreads();
    mx = red[0];
#pragma unroll
    for (int i = 1; i < 8; i++) mx = fmaxf(mx, red[i]);

    float s = 0.f;
#pragma unroll
    for (int i = 0; i < 8; i++) { v[i] = __expf(v[i] - mx); s += v[i]; }
#pragma unroll
    for (int o = 16; o; o >>= 1) s += __shfl_xor_sync(0xffffffffu, s, o);
    __syncthreads();
    if ((t & 31) == 0) red[t >> 5] = s;
    __syncthreads();
    s = 0.f;
#pragma unroll
    for (int i = 0; i < 8; i++) s += red[i];

    const float inv = 1.0f / s;
#pragma unroll
    for (int i = 0; i < 8; i++) p[t + 256 * i] = v[i] * inv;
}

// ---------------------------------------------------------------------------
// LayerNorm over HIDD=1024.
// ---------------------------------------------------------------------------
__global__ void __launch_bounds__(256)
ln_k(const float* __restrict__ X, const float* __restrict__ gam,
     const float* __restrict__ bet, float* __restrict__ Y)
{
    const float* x = X + (size_t)blockIdx.x * HIDD;
    float*       y = Y + (size_t)blockIdx.x * HIDD;
    const int t = threadIdx.x;
    __shared__ float red[8];

    float v[4];
    float s = 0.f;
#pragma unroll
    for (int i = 0; i < 4; i++) { v[i] = x[t + 256 * i]; s += v[i]; }
#pragma unroll
    for (int o = 16; o; o >>= 1) s += __shfl_xor_sync(0xffffffffu, s, o);
    if ((t & 31) == 0) red[t >> 5] = s;
    __syncthreads();
    s = 0.f;
#pragma unroll
    for (int i = 0; i < 8; i++) s += red[i];
    const float mean = s * (1.0f / HIDD);

    float vs = 0.f;
#pragma unroll
    for (int i = 0; i < 4; i++) { float d = v[i] - mean; vs += d * d; }
#pragma unroll
    for (int o = 16; o; o >>= 1) vs += __shfl_xor_sync(0xffffffffu, vs, o);
    __syncthreads();
    if ((t & 31) == 0) red[t >> 5] = vs;
    __syncthreads();
    vs = 0.f;
#pragma unroll
    for (int i = 0; i < 8; i++) vs += red[i];
    const float inv = rsqrtf(vs * (1.0f / HIDD) + 1e-5f);

#pragma unroll
    for (int i = 0; i < 4; i++) {
        int c = t + 256 * i;
        y[c] = (v[i] - mean) * inv * gam[c] + bet[c];
    }
}

// ---------------------------------------------------------------------------
#define SMEM_128 73728
#define SMEM_64  55296

extern "C" void kernel_launch(void* const* d_in, const int* in_sizes, int n_in,
                              void* d_out, int out_size)
{
    const float* tgt    = (const float*)d_in[0];
    const float* enc    = (const float*)d_in[1];
    const int*   tmask  = (const int*)  d_in[2];
    const int*   smask  = (const int*)  d_in[3];
    const float* sa_wq  = (const float*)d_in[4],  *sa_bq = (const float*)d_in[5];
    const float* sa_wk  = (const float*)d_in[6],  *sa_bk = (const float*)d_in[7];
    const float* sa_wv  = (const float*)d_in[8],  *sa_bv = (const float*)d_in[9];
    const float* sa_wo  = (const float*)d_in[10], *sa_bo = (const float*)d_in[11];
    const float* ea_wq  = (const float*)d_in[12], *ea_bq = (const float*)d_in[13];
    const float* ea_wk  = (const float*)d_in[14], *ea_bk = (const float*)d_in[15];
    const float* ea_wv  = (const float*)d_in[16], *ea_bv = (const float*)d_in[17];
    const float* ea_wo  = (const float*)d_in[18], *ea_bo = (const float*)d_in[19];
    const float* ffn_w1 = (const float*)d_in[20], *ffn_b1 = (const float*)d_in[21];
    const float* ffn_w2 = (const float*)d_in[22], *ffn_b2 = (const float*)d_in[23];
    const float* ln1_g  = (const float*)d_in[24], *ln1_b = (const float*)d_in[25];
    const float* ln2_g  = (const float*)d_in[26], *ln2_b = (const float*)d_in[27];
    const float* ln3_g  = (const float*)d_in[28], *ln3_b = (const float*)d_in[29];

    float* out     = (float*)d_out;
    float* att_out = out + (size_t)BC * LSEQ * HIDD;

    float *q, *k, *vt, *ao, *h, *ffn, *sc, *wt;
    cudaGetSymbolAddress((void**)&q,   g_q);
    cudaGetSymbolAddress((void**)&k,   g_k);
    cudaGetSymbolAddress((void**)&vt,  g_vt);
    cudaGetSymbolAddress((void**)&ao,  g_ao);
    cudaGetSymbolAddress((void**)&h,   g_h);
    cudaGetSymbolAddress((void**)&ffn, g_ffn);
    cudaGetSymbolAddress((void**)&sc,  g_sc);
    cudaGetSymbolAddress((void**)&wt,  g_wt);

    const size_t M1 = 1024 * 1024;
    float* wt_saq = wt + 0 * M1; float* wt_sak = wt + 1 * M1;
    float* wt_sav = wt + 2 * M1; float* wt_sao = wt + 3 * M1;
    float* wt_eaq = wt + 4 * M1; float* wt_eak = wt + 5 * M1;
    float* wt_eav = wt + 6 * M1; float* wt_eao = wt + 7 * M1;
    float* wt_f1  = wt + 8 * M1;            // [4096][1024]
    float* wt_f2  = wt + 12 * M1;           // [1024][4096]

    static bool attr_done = false;
    if (!attr_done) {
        cudaFuncSetAttribute(tc_gemm<1,128>, cudaFuncAttributeMaxDynamicSharedMemorySize, SMEM_128);
        cudaFuncSetAttribute(tc_gemm<2,128>, cudaFuncAttributeMaxDynamicSharedMemorySize, SMEM_128);
        cudaFuncSetAttribute(tc_gemm<3,128>, cudaFuncAttributeMaxDynamicSharedMemorySize, SMEM_128);
        cudaFuncSetAttribute(tc_gemm<4,128>, cudaFuncAttributeMaxDynamicSharedMemorySize, SMEM_128);
        cudaFuncSetAttribute(tc_gemm<5,128>, cudaFuncAttributeMaxDynamicSharedMemorySize, SMEM_128);
        cudaFuncSetAttribute(tc_gemm<6,64>,  cudaFuncAttributeMaxDynamicSharedMemorySize, SMEM_64);
        attr_done = true;
    }

    const dim3 tb(32, 8);
    transpose_k<<<dim3(32, 32), tb>>>(sa_wq, wt_saq, 1024, 1024);
    transpose_k<<<dim3(32, 32), tb>>>(sa_wk, wt_sak, 1024, 1024);
    transpose_k<<<dim3(32, 32), tb>>>(sa_wv, wt_sav, 1024, 1024);
    transpose_k<<<dim3(32, 32), tb>>>(sa_wo, wt_sao, 1024, 1024);
    transpose_k<<<dim3(32, 32), tb>>>(ea_wq, wt_eaq, 1024, 1024);
    transpose_k<<<dim3(32, 32), tb>>>(ea_wk, wt_eak, 1024, 1024);
    transpose_k<<<dim3(32, 32), tb>>>(ea_wv, wt_eav, 1024, 1024);
    transpose_k<<<dim3(32, 32), tb>>>(ea_wo, wt_eao, 1024, 1024);
    transpose_k<<<dim3(128, 32), tb>>>(ffn_w1, wt_f1, 1024, 4096);
    transpose_k<<<dim3(32, 128), tb>>>(ffn_w2, wt_f2, 4096, 1024);

    const dim3 gp (8, 32, 1);
    const dim3 gf1(32, 32, 1);
    const dim3 gsc(16, 16, BC * NH);
    const dim3 gpv(1, 16, BC * NH);
    const long long ABq = (long long)LSEQ * HD;
    const long long ABs = (long long)LSEQ * LSEQ;
    const long long ABv = (long long)HD * LSEQ;

    // ---- self-attention ----
    tc_gemm<1,128><<<gp, 256, SMEM_128>>>(tgt, wt_saq, sa_bq, nullptr, nullptr, q,  1024, 1024, 1024, 1024, 0, 0);
    tc_gemm<1,128><<<gp, 256, SMEM_128>>>(tgt, wt_sak, sa_bk, nullptr, nullptr, k,  1024, 1024, 1024, 1024, 0, 0);
    tc_gemm<4,128><<<gp, 256, SMEM_128>>>(tgt, wt_sav, sa_bv, nullptr, nullptr, vt, 1024, 1024, 1024, 1024, 0, 0);
    tc_gemm<5,128><<<gsc, 256, SMEM_128>>>(q, k, nullptr, nullptr, tmask, sc, 64, 64, 64, 2048, ABq, ABq);
    softmax_k<<<BC * NH * LSEQ, 256>>>(sc);
    tc_gemm<6,64><<<gpv, 256, SMEM_64>>>(sc, vt, nullptr, nullptr, nullptr, ao, 2048, 2048, 2048, 64, ABs, ABv);
    tc_gemm<3,128><<<gp, 256, SMEM_128>>>(ao, wt_sao, sa_bo, tgt, nullptr, h, 1024, 1024, 1024, 1024, 0, 0);
    ln_k<<<MROWS, 256>>>(h, ln1_g, ln1_b, h);

    // ---- cross-attention (probs straight into d_out region) ----
    tc_gemm<1,128><<<gp, 256, SMEM_128>>>(h,   wt_eaq, ea_bq, nullptr, nullptr, q,  1024, 1024, 1024, 1024, 0, 0);
    tc_gemm<1,128><<<gp, 256, SMEM_128>>>(enc, wt_eak, ea_bk, nullptr, nullptr, k,  1024, 1024, 1024, 1024, 0, 0);
    tc_gemm<4,128><<<gp, 256, SMEM_128>>>(enc, wt_eav, ea_bv, nullptr, nullptr, vt, 1024, 1024, 1024, 1024, 0, 0);
    tc_gemm<5,128><<<gsc, 256, SMEM_128>>>(q, k, nullptr, nullptr, smask, att_out, 64, 64, 64, 2048, ABq, ABq);
    softmax_k<<<BC * NH * LSEQ, 256>>>(att_out);
    tc_gemm<6,64><<<gpv, 256, SMEM_64>>>(att_out, vt, nullptr, nullptr, nullptr, ao, 2048, 2048, 2048, 64, ABs, ABv);
    tc_gemm<3,128><<<gp, 256, SMEM_128>>>(ao, wt_eao, ea_bo, h, nullptr, h, 1024, 1024, 1024, 1024, 0, 0);
    ln_k<<<MROWS, 256>>>(h, ln2_g, ln2_b, h);

    // ---- FFN ----
    tc_gemm<2,128><<<gf1, 256, SMEM_128>>>(h, wt_f1, ffn_b1, nullptr, nullptr, ffn, 1024, 1024, 1024, 4096, 0, 0);
    tc_gemm<3,128><<<gp, 256, SMEM_128>>>(ffn, wt_f2, ffn_b2, h, nullptr, h, 4096, 4096, 4096, 1024, 0, 0);
    ln_k<<<MROWS, 256>>>(h, ln3_g, ln3_b, out);
}

// round 4
// speedup vs baseline: 1.5943x; 1.1826x over previous
#include <cuda_runtime.h>
#include <mma.h>
#include <cstdint>
#include <math.h>

using namespace nvcuda;

#define BC    2
#define LSEQ  2048
#define HIDD  1024
#define NH    16
#define HD    64
#define PFF   4096
#define MROWS (BC * LSEQ)
#define ATT_ELEMS ((size_t)BC * NH * LSEQ * LSEQ)

// ---------------- device scratch ----------------
__device__ float g_q  [MROWS * HIDD];
__device__ float g_k  [MROWS * HIDD];
__device__ float g_vt [MROWS * HIDD];        // V in [z][d][l] transposed layout
__device__ float g_ao [MROWS * HIDD];
__device__ float g_h  [MROWS * HIDD];
__device__ float g_ffn[(size_t)MROWS * PFF];
__device__ float g_sc [ATT_ELEMS];           // self-attn scores/probs
__device__ float g_wt [16 * 1024 * 1024];    // transposed weights [N][K]

// ---------------- helpers ----------------
__device__ __forceinline__ void cp16(uint32_t dst, const float* src) {
    asm volatile("cp.async.cg.shared.global [%0], [%1], 16;"
        :: "r"(dst), "l"(__cvta_generic_to_global(src)));
}
__device__ __forceinline__ uint32_t smem_u32(const void* p) {
    uint32_t a;
    asm("{ .reg .u64 t; cvta.to.shared.u64 t, %1; cvt.u32.u64 %0, t; }"
        : "=r"(a) : "l"(p));
    return a;
}

// ---------------------------------------------------------------------------
// wmma tf32 GEMM: D[128 x NT] = A[128,K] @ B[NT,K]^T   (both K-major)
// 3-stage cp.async pipeline, 8 warps.  NT=256: warp tile 64x64.
// MODE 1: attn-layout out + bias            (cross-Q proj)
// MODE 2: relu + bias                       (FFN up)
// MODE 3: bias + residual, row-major out    (out projections / FFN down)
// MODE 5: scores: *0.125 + mask, batched
// MODE 6: PV out -> O[b*LSEQ+q][h*64+d], batched   (NT=64)
// MODE 7: fused self-QKV: seg0->Q(attn), seg1->K(attn), seg2->V^T
// MODE 8: fused cross-KV: seg0->K(attn), seg1->V^T
// ---------------------------------------------------------------------------
template<int MODE, int NT>
__global__ void __launch_bounds__(256)
tc_gemm(const float* __restrict__ A, const float* __restrict__ B,
        const float* __restrict__ bias0, const float* __restrict__ bias1,
        const float* __restrict__ bias2, const float* __restrict__ Rres,
        const int* __restrict__ mask,
        float* __restrict__ C0, float* __restrict__ C1, float* __restrict__ C2,
        int K, int lda, int ldb, int ncols,
        long long aBatch, long long bBatch)
{
    constexpr int WY  = (NT >= 128) ? 2 : 4;
    constexpr int WX  = 8 / WY;
    constexpr int WTM = 128 / WY;
    constexpr int WTN = NT / WX;
    constexpr int FM  = WTM / 16;
    constexpr int FN  = WTN / 16;
    constexpr int LDS_ = 36;
    constexpr int ASZ = 128 * LDS_;
    constexpr int BSZ = NT * LDS_;
    constexpr int CH  = ASZ + BSZ;
    constexpr int STAGES = 3;
    constexpr int STG_R = NT + 4;
    constexpr int STG_C = 132;

    extern __shared__ float sm[];
    const uint32_t sb = smem_u32(sm);
    const int t = threadIdx.x, w = t >> 5;
    const int wy = w % WY, wx = w / WY;
    const int m0 = blockIdx.y * 128, n0 = blockIdx.x * NT;
    const int z  = blockIdx.z;

    const float* Ab = A + (size_t)z * aBatch;
    const float* Bb = B + (size_t)z * bBatch;

    wmma::fragment<wmma::accumulator, 16, 16, 8, float> cf[FM][FN];
#pragma unroll
    for (int i = 0; i < FM; i++)
#pragma unroll
        for (int j = 0; j < FN; j++) wmma::fill_fragment(cf[i][j], 0.0f);

    auto load_chunk = [&](int ci, int s) {
        const int k0 = ci * 32;
        const uint32_t abase = sb + (uint32_t)(s * CH) * 4u;
#pragma unroll
        for (int j = 0; j < 4; j++) {
            int id = j * 256 + t, row = id >> 3, cc = id & 7;
            cp16(abase + (uint32_t)(row * LDS_ + cc * 4) * 4u,
                 Ab + (size_t)(m0 + row) * lda + k0 + cc * 4);
        }
        const uint32_t bbase = abase + (uint32_t)ASZ * 4u;
#pragma unroll
        for (int j = 0; j < NT / 32; j++) {
            int id = j * 256 + t, row = id >> 3, cc = id & 7;
            cp16(bbase + (uint32_t)(row * LDS_ + cc * 4) * 4u,
                 Bb + (size_t)(n0 + row) * ldb + k0 + cc * 4);
        }
        asm volatile("cp.async.commit_group;");
    };

    const int nch = K / 32;
#pragma unroll
    for (int s = 0; s < STAGES - 1; s++)
        if (s < nch) load_chunk(s, s);

    for (int i = 0; i < nch; i++) {
        if (i + STAGES - 1 < nch) load_chunk(i + STAGES - 1, (i + STAGES - 1) % STAGES);
        else asm volatile("cp.async.commit_group;");
        asm volatile("cp.async.wait_group 2;");
        __syncthreads();
        const float* Ast = sm + (i % STAGES) * CH;
        const float* Bst = Ast + ASZ;
#pragma unroll
        for (int ks = 0; ks < 4; ks++) {
            wmma::fragment<wmma::matrix_a, 16, 16, 8, wmma::precision::tf32, wmma::row_major> af[FM];
#pragma unroll
            for (int fm = 0; fm < FM; fm++)
                wmma::load_matrix_sync(af[fm], Ast + (wy * WTM + fm * 16) * LDS_ + ks * 8, LDS_);
#pragma unroll
            for (int fn = 0; fn < FN; fn++) {
                wmma::fragment<wmma::matrix_b, 16, 16, 8, wmma::precision::tf32, wmma::col_major> bf;
                wmma::load_matrix_sync(bf, Bst + (wx * WTN + fn * 16) * LDS_ + ks * 8, LDS_);
#pragma unroll
                for (int fm = 0; fm < FM; fm++)
                    wmma::mma_sync(cf[fm][fn], af[fm], bf, cf[fm][fn]);
            }
        }
        __syncthreads();
    }
    __syncthreads();

    // ---- block-uniform epilogue routing ----
    int em = MODE, nrel = n0;
    const float* bb = bias0;
    float* Cc = C0;
    if (MODE == 7) {
        int seg = n0 >> 10; nrel = n0 & 1023;
        em = (seg == 2) ? 4 : 1;
        Cc = (seg == 0) ? C0 : (seg == 1) ? C1 : C2;
        bb = (seg == 0) ? bias0 : (seg == 1) ? bias1 : bias2;
    }
    if (MODE == 8) {
        int seg = n0 >> 10; nrel = n0 & 1023;
        em = seg ? 4 : 1;
        Cc = seg ? C1 : C0;
        bb = seg ? bias1 : bias0;
    }

    float* stg = sm;
    if (em == 4) {
        // stage col-major: stg[col*132 + row]
#pragma unroll
        for (int fm = 0; fm < FM; fm++)
#pragma unroll
            for (int fn = 0; fn < FN; fn++)
                wmma::store_matrix_sync(stg + (wx * WTN + fn * 16) * STG_C + wy * WTM + fm * 16,
                                        cf[fm][fn], STG_C, wmma::mem_col_major);
        __syncthreads();
        const int b = m0 >> 11, lbase = m0 & 2047;
#pragma unroll
        for (int p = 0; p < NT / 8; p++) {
            int idx = p * 256 + t;
            int dcol = idx >> 5, lq = idx & 31, l4 = lq * 4;
            int nr = nrel + dcol, h = nr >> 6, dd = nr & 63;
            float bv = __ldg(&bb[nr]);
            float4 o = *(const float4*)&stg[dcol * STG_C + l4];
            o.x += bv; o.y += bv; o.z += bv; o.w += bv;
            *(float4*)&Cc[(((size_t)(b * NH + h)) * HD + dd) * LSEQ + lbase + l4] = o;
        }
    } else {
#pragma unroll
        for (int fm = 0; fm < FM; fm++)
#pragma unroll
            for (int fn = 0; fn < FN; fn++)
                wmma::store_matrix_sync(stg + (wy * WTM + fm * 16) * STG_R + wx * WTN + fn * 16,
                                        cf[fm][fn], STG_R, wmma::mem_row_major);
        __syncthreads();
        constexpr int QPR = NT / 4;
#pragma unroll
        for (int p = 0; p < (128 * QPR) / 256; p++) {
            int idx = p * 256 + t;
            int rr = idx / QPR;
            int cq = (idx % QPR) * 4;
            float4 o = *(const float4*)&stg[rr * STG_R + cq];
            float vv[4] = {o.x, o.y, o.z, o.w};
#pragma unroll
            for (int c2 = 0; c2 < 4; c2++) {
                if (em == 1)                 vv[c2] += __ldg(&bb[nrel + cq + c2]);
                if (em == 2 || em == 3)      vv[c2] += __ldg(&bb[n0 + cq + c2]);
                if (em == 2)                 vv[c2] = fmaxf(vv[c2], 0.f);
                if (em == 5) {
                    vv[c2] *= 0.125f;
                    if (__ldg(&mask[(z >> 4) * LSEQ + n0 + cq + c2]) == 0) vv[c2] = -1e30f;
                }
            }
            o.x = vv[0]; o.y = vv[1]; o.z = vv[2]; o.w = vv[3];
            if (em == 3) {
                const float4 rv = *(const float4*)&Rres[(size_t)(m0 + rr) * ncols + n0 + cq];
                o.x += rv.x; o.y += rv.y; o.z += rv.z; o.w += rv.w;
                *(float4*)&Cc[(size_t)(m0 + rr) * ncols + n0 + cq] = o;
            } else if (em == 1) {
                int m = m0 + rr, b = m >> 11, l = m & 2047;
                int nr = nrel + cq, h = nr >> 6, d = nr & 63;
                *(float4*)&Cc[(((size_t)(b * NH + h)) * LSEQ + l) * HD + d] = o;
            } else if (em == 5) {
                *(float4*)&Cc[(size_t)z * LSEQ * LSEQ + (size_t)(m0 + rr) * LSEQ + n0 + cq] = o;
            } else if (em == 6) {
                int b = z >> 4, h = z & 15;
                *(float4*)&Cc[((size_t)(b * LSEQ + m0 + rr)) * HIDD + h * HD + n0 + cq] = o;
            } else { // em == 2
                *(float4*)&Cc[(size_t)(m0 + rr) * ncols + n0 + cq] = o;
            }
        }
    }
}

// ---------------------------------------------------------------------------
__global__ void transpose_k(const float* __restrict__ W, float* __restrict__ Wt,
                            int Rk, int Cn)
{
    __shared__ float tile[32][33];
    const int c0 = blockIdx.x * 32, r0 = blockIdx.y * 32;
    const int x = threadIdx.x, y = threadIdx.y;
#pragma unroll
    for (int j = 0; j < 32; j += 8)
        tile[y + j][x] = W[(size_t)(r0 + y + j) * Cn + c0 + x];
    __syncthreads();
#pragma unroll
    for (int j = 0; j < 32; j += 8)
        Wt[(size_t)(c0 + y + j) * Rk + r0 + x] = tile[x][y + j];
}

// ---------------------------------------------------------------------------
__global__ void __launch_bounds__(256) softmax_k(float* __restrict__ S)
{
    float* p = S + (size_t)blockIdx.x * LSEQ;
    const int t = threadIdx.x;
    __shared__ float red[8];

    float v[8];
    float mx = -3.4e38f;
#pragma unroll
    for (int i = 0; i < 8; i++) { v[i] = p[t + 256 * i]; mx = fmaxf(mx, v[i]); }
#pragma unroll
    for (int o = 16; o; o >>= 1) mx = fmaxf(mx, __shfl_xor_sync(0xffffffffu, mx, o));
    if ((t & 31) == 0) red[t >> 5] = mx;
    __syncthreads();
    mx = red[0];
#pragma unroll
    for (int i = 1; i < 8; i++) mx = fmaxf(mx, red[i]);

    float s = 0.f;
#pragma unroll
    for (int i = 0; i < 8; i++) { v[i] = __expf(v[i] - mx); s += v[i]; }
#pragma unroll
    for (int o = 16; o; o >>= 1) s += __shfl_xor_sync(0xffffffffu, s, o);
    __syncthreads();
    if ((t & 31) == 0) red[t >> 5] = s;
    __syncthreads();
    s = 0.f;
#pragma unroll
    for (int i = 0; i < 8; i++) s += red[i];

    const float inv = 1.0f / s;
#pragma unroll
    for (int i = 0; i < 8; i++) p[t + 256 * i] = v[i] * inv;
}

// ---------------------------------------------------------------------------
__global__ void __launch_bounds__(256)
ln_k(const float* __restrict__ X, const float* __restrict__ gam,
     const float* __restrict__ bet, float* __restrict__ Y)
{
    const float* x = X + (size_t)blockIdx.x * HIDD;
    float*       y = Y + (size_t)blockIdx.x * HIDD;
    const int t = threadIdx.x;
    __shared__ float red[8];

    float v[4];
    float s = 0.f;
#pragma unroll
    for (int i = 0; i < 4; i++) { v[i] = x[t + 256 * i]; s += v[i]; }
#pragma unroll
    for (int o = 16; o; o >>= 1) s += __shfl_xor_sync(0xffffffffu, s, o);
    if ((t & 31) == 0) red[t >> 5] = s;
    __syncthreads();
    s = 0.f;
#pragma unroll
    for (int i = 0; i < 8; i++) s += red[i];
    const float mean = s * (1.0f / HIDD);

    float vs = 0.f;
#pragma unroll
    for (int i = 0; i < 4; i++) { float d = v[i] - mean; vs += d * d; }
#pragma unroll
    for (int o = 16; o; o >>= 1) vs += __shfl_xor_sync(0xffffffffu, vs, o);
    __syncthreads();
    if ((t & 31) == 0) red[t >> 5] = vs;
    __syncthreads();
    vs = 0.f;
#pragma unroll
    for (int i = 0; i < 8; i++) vs += red[i];
    const float inv = rsqrtf(vs * (1.0f / HIDD) + 1e-5f);

#pragma unroll
    for (int i = 0; i < 4; i++) {
        int c = t + 256 * i;
        y[c] = (v[i] - mean) * inv * gam[c] + bet[c];
    }
}

// ---------------------------------------------------------------------------
#define SMEM_256 165888   // 3 stages * (128+256)*36 floats
#define SMEM_64  82944    // 3 stages * (128+64)*36 floats

extern "C" void kernel_launch(void* const* d_in, const int* in_sizes, int n_in,
                              void* d_out, int out_size)
{
    const float* tgt    = (const float*)d_in[0];
    const float* enc    = (const float*)d_in[1];
    const int*   tmask  = (const int*)  d_in[2];
    const int*   smask  = (const int*)  d_in[3];
    const float* sa_wq  = (const float*)d_in[4],  *sa_bq = (const float*)d_in[5];
    const float* sa_wk  = (const float*)d_in[6],  *sa_bk = (const float*)d_in[7];
    const float* sa_wv  = (const float*)d_in[8],  *sa_bv = (const float*)d_in[9];
    const float* sa_wo  = (const float*)d_in[10], *sa_bo = (const float*)d_in[11];
    const float* ea_wq  = (const float*)d_in[12], *ea_bq = (const float*)d_in[13];
    const float* ea_wk  = (const float*)d_in[14], *ea_bk = (const float*)d_in[15];
    const float* ea_wv  = (const float*)d_in[16], *ea_bv = (const float*)d_in[17];
    const float* ea_wo  = (const float*)d_in[18], *ea_bo = (const float*)d_in[19];
    const float* ffn_w1 = (const float*)d_in[20], *ffn_b1 = (const float*)d_in[21];
    const float* ffn_w2 = (const float*)d_in[22], *ffn_b2 = (const float*)d_in[23];
    const float* ln1_g  = (const float*)d_in[24], *ln1_b = (const float*)d_in[25];
    const float* ln2_g  = (const float*)d_in[26], *ln2_b = (const float*)d_in[27];
    const float* ln3_g  = (const float*)d_in[28], *ln3_b = (const float*)d_in[29];

    float* out     = (float*)d_out;
    float* att_out = out + (size_t)BC * LSEQ * HIDD;

    float *q, *k, *vt, *ao, *h, *ffn, *sc, *wt;
    cudaGetSymbolAddress((void**)&q,   g_q);
    cudaGetSymbolAddress((void**)&k,   g_k);
    cudaGetSymbolAddress((void**)&vt,  g_vt);
    cudaGetSymbolAddress((void**)&ao,  g_ao);
    cudaGetSymbolAddress((void**)&h,   g_h);
    cudaGetSymbolAddress((void**)&ffn, g_ffn);
    cudaGetSymbolAddress((void**)&sc,  g_sc);
    cudaGetSymbolAddress((void**)&wt,  g_wt);

    const size_t M1 = 1024 * 1024;
    float* wt_saqkv = wt + 0 * M1;          // saq, sak, sav contiguous [3072][1024]
    float* wt_sao   = wt + 3 * M1;
    float* wt_eaq   = wt + 4 * M1;
    float* wt_eakv  = wt + 5 * M1;          // eak, eav contiguous [2048][1024]
    float* wt_eao   = wt + 7 * M1;
    float* wt_f1    = wt + 8 * M1;          // [4096][1024]
    float* wt_f2    = wt + 12 * M1;         // [1024][4096]

    static bool attr_done = false;
    if (!attr_done) {
        cudaFuncSetAttribute(tc_gemm<7,256>, cudaFuncAttributeMaxDynamicSharedMemorySize, SMEM_256);
        cudaFuncSetAttribute(tc_gemm<8,256>, cudaFuncAttributeMaxDynamicSharedMemorySize, SMEM_256);
        cudaFuncSetAttribute(tc_gemm<1,256>, cudaFuncAttributeMaxDynamicSharedMemorySize, SMEM_256);
        cudaFuncSetAttribute(tc_gemm<2,256>, cudaFuncAttributeMaxDynamicSharedMemorySize, SMEM_256);
        cudaFuncSetAttribute(tc_gemm<3,256>, cudaFuncAttributeMaxDynamicSharedMemorySize, SMEM_256);
        cudaFuncSetAttribute(tc_gemm<5,256>, cudaFuncAttributeMaxDynamicSharedMemorySize, SMEM_256);
        cudaFuncSetAttribute(tc_gemm<6,64>,  cudaFuncAttributeMaxDynamicSharedMemorySize, SMEM_64);
        attr_done = true;
    }

    const dim3 tb(32, 8);
    transpose_k<<<dim3(32, 32), tb>>>(sa_wq, wt_saqkv + 0 * M1, 1024, 1024);
    transpose_k<<<dim3(32, 32), tb>>>(sa_wk, wt_saqkv + 1 * M1, 1024, 1024);
    transpose_k<<<dim3(32, 32), tb>>>(sa_wv, wt_saqkv + 2 * M1, 1024, 1024);
    transpose_k<<<dim3(32, 32), tb>>>(sa_wo, wt_sao, 1024, 1024);
    transpose_k<<<dim3(32, 32), tb>>>(ea_wq, wt_eaq, 1024, 1024);
    transpose_k<<<dim3(32, 32), tb>>>(ea_wk, wt_eakv + 0 * M1, 1024, 1024);
    transpose_k<<<dim3(32, 32), tb>>>(ea_wv, wt_eakv + 1 * M1, 1024, 1024);
    transpose_k<<<dim3(32, 32), tb>>>(ea_wo, wt_eao, 1024, 1024);
    transpose_k<<<dim3(128, 32), tb>>>(ffn_w1, wt_f1, 1024, 4096);
    transpose_k<<<dim3(32, 128), tb>>>(ffn_w2, wt_f2, 4096, 1024);

    const dim3 gqkv(12, 32, 1);             // N=3072
    const dim3 gkv (8, 32, 1);              // N=2048
    const dim3 gp  (4, 32, 1);              // N=1024
    const dim3 gf1 (16, 32, 1);             // N=4096
    const dim3 gsc (8, 16, BC * NH);        // scores 2048x2048 per z
    const dim3 gpv (1, 16, BC * NH);        // PV
    const long long ABq = (long long)LSEQ * HD;
    const long long ABs = (long long)LSEQ * LSEQ;
    const long long ABv = (long long)HD * LSEQ;

    // ---- self-attention ----
    tc_gemm<7,256><<<gqkv, 256, SMEM_256>>>(tgt, wt_saqkv, sa_bq, sa_bk, sa_bv, nullptr, nullptr,
                                            q, k, vt, 1024, 1024, 1024, 0, 0, 0);
    tc_gemm<5,256><<<gsc, 256, SMEM_256>>>(q, k, nullptr, nullptr, nullptr, nullptr, tmask,
                                           sc, nullptr, nullptr, 64, 64, 64, 2048, ABq, ABq);
    softmax_k<<<BC * NH * LSEQ, 256>>>(sc);
    tc_gemm<6,64><<<gpv, 256, SMEM_64>>>(sc, vt, nullptr, nullptr, nullptr, nullptr, nullptr,
                                         ao, nullptr, nullptr, 2048, 2048, 2048, 64, ABs, ABv);
    tc_gemm<3,256><<<gp, 256, SMEM_256>>>(ao, wt_sao, sa_bo, nullptr, nullptr, tgt, nullptr,
                                          h, nullptr, nullptr, 1024, 1024, 1024, 1024, 0, 0);
    ln_k<<<MROWS, 256>>>(h, ln1_g, ln1_b, h);

    // ---- cross-attention ----
    tc_gemm<1,256><<<gp, 256, SMEM_256>>>(h, wt_eaq, ea_bq, nullptr, nullptr, nullptr, nullptr,
                                          q, nullptr, nullptr, 1024, 1024, 1024, 0, 0, 0);
    tc_gemm<8,256><<<gkv, 256, SMEM_256>>>(enc, wt_eakv, ea_bk, ea_bv, nullptr, nullptr, nullptr,
                                           k, vt, nullptr, 1024, 1024, 1024, 0, 0, 0);
    tc_gemm<5,256><<<gsc, 256, SMEM_256>>>(q, k, nullptr, nullptr, nullptr, nullptr, smask,
                                           att_out, nullptr, nullptr, 64, 64, 64, 2048, ABq, ABq);
    softmax_k<<<BC * NH * LSEQ, 256>>>(att_out);
    tc_gemm<6,64><<<gpv, 256, SMEM_64>>>(att_out, vt, nullptr, nullptr, nullptr, nullptr, nullptr,
                                         ao, nullptr, nullptr, 2048, 2048, 2048, 64, ABs, ABv);
    tc_gemm<3,256><<<gp, 256, SMEM_256>>>(ao, wt_eao, ea_bo, nullptr, nullptr, h, nullptr,
                                          h, nullptr, nullptr, 1024, 1024, 1024, 1024, 0, 0);
    ln_k<<<MROWS, 256>>>(h, ln2_g, ln2_b, h);

    // ---- FFN ----
    tc_gemm<2,256><<<gf1, 256, SMEM_256>>>(h, wt_f1, ffn_b1, nullptr, nullptr, nullptr, nullptr,
                                           ffn, nullptr, nullptr, 1024, 1024, 1024, 4096, 0, 0);
    tc_gemm<3,256><<<gp, 256, SMEM_256>>>(ffn, wt_f2, ffn_b2, nullptr, nullptr, h, nullptr,
                                          h, nullptr, nullptr, 4096, 4096, 4096, 1024, 0, 0);
    ln_k<<<MROWS, 256>>>(h, ln3_g, ln3_b, out);
}